// round 3
// baseline (speedup 1.0000x reference)
#include <cuda_runtime.h>
#include <math.h>

#define NN 100000
#define NE 800000
#define DD 96
#define D4 (DD/4)   // 24 float4 per row

// ---- scratch (static device globals; no allocation at runtime) ----
__device__ __align__(16) float g_h[(size_t)NN * DD];     // GEMM output / reused as x1
__device__ __align__(16) float g_agg[(size_t)NN * DD];   // aggregation buffer / reused as h2
__device__ int   g_deg[NN];
__device__ float g_dinv[NN];

// ---------------- degree / norm ----------------
__global__ void zero_deg_kernel() {
    int i = blockIdx.x * blockDim.x + threadIdx.x;
    if (i < NN) g_deg[i] = 0;
}

__global__ void count_deg_kernel(const int* __restrict__ dst) {
    int e = blockIdx.x * blockDim.x + threadIdx.x;
    if (e < NE) {
        int d = dst[e];
        if ((unsigned)d < NN) atomicAdd(&g_deg[d], 1);
    }
}

__global__ void dinv_kernel() {
    int i = blockIdx.x * blockDim.x + threadIdx.x;
    if (i < NN) g_dinv[i] = rsqrtf((float)(g_deg[i] + 1));  // +1 self-loop
}

// ---------------- GEMM: out[N,96] = X[N,96] @ W[96,96] ----------------
__global__ void __launch_bounds__(256, 1)
gemm96(const float* __restrict__ X, const float* __restrict__ W, float* __restrict__ out) {
    __shared__ float Ws[DD * DD];  // 36 KB
    for (int i = threadIdx.x; i < DD * DD / 4; i += 256)
        ((float4*)Ws)[i] = ((const float4*)W)[i];
    __syncthreads();

    const int tc   = threadIdx.x & 31;
    const int wid  = threadIdx.x >> 5;
    const int row0 = blockIdx.x * 64 + wid * 8;

    float acc[8][3];
#pragma unroll
    for (int i = 0; i < 8; i++) { acc[i][0] = 0.f; acc[i][1] = 0.f; acc[i][2] = 0.f; }

#pragma unroll 1
    for (int k4 = 0; k4 < D4; k4++) {
        float b[4][3];
#pragma unroll
        for (int kk = 0; kk < 4; kk++) {
            int k = k4 * 4 + kk;
            b[kk][0] = Ws[k * DD + tc];
            b[kk][1] = Ws[k * DD + tc + 32];
            b[kk][2] = Ws[k * DD + tc + 64];
        }
#pragma unroll
        for (int i = 0; i < 8; i++) {
            int r = row0 + i;
            if (r < NN) {
                float4 a = ((const float4*)(X + (size_t)r * DD))[k4];
                acc[i][0] = fmaf(a.x, b[0][0], acc[i][0]);
                acc[i][1] = fmaf(a.x, b[0][1], acc[i][1]);
                acc[i][2] = fmaf(a.x, b[0][2], acc[i][2]);
                acc[i][0] = fmaf(a.y, b[1][0], acc[i][0]);
                acc[i][1] = fmaf(a.y, b[1][1], acc[i][1]);
                acc[i][2] = fmaf(a.y, b[1][2], acc[i][2]);
                acc[i][0] = fmaf(a.z, b[2][0], acc[i][0]);
                acc[i][1] = fmaf(a.z, b[2][1], acc[i][1]);
                acc[i][2] = fmaf(a.z, b[2][2], acc[i][2]);
                acc[i][0] = fmaf(a.w, b[3][0], acc[i][0]);
                acc[i][1] = fmaf(a.w, b[3][1], acc[i][1]);
                acc[i][2] = fmaf(a.w, b[3][2], acc[i][2]);
            }
        }
    }
#pragma unroll
    for (int i = 0; i < 8; i++) {
        int r = row0 + i;
        if (r < NN) {
            out[(size_t)r * DD + tc]      = acc[i][0];
            out[(size_t)r * DD + tc + 32] = acc[i][1];
            out[(size_t)r * DD + tc + 64] = acc[i][2];
        }
    }
}

// ---------------- self-loop init: agg = h * dinv^2 + bias ----------------
__global__ void selfloop_init(const float* __restrict__ h, const float* __restrict__ bias,
                              float* __restrict__ agg) {
    int idx = blockIdx.x * blockDim.x + threadIdx.x;   // float4 index over N*24
    if (idx >= NN * D4) return;
    int node = idx / D4;
    int c4   = idx - node * D4;
    float di = g_dinv[node];
    float w  = di * di;
    float4 v = ((const float4*)h)[idx];
    float4 bb = ((const float4*)bias)[c4];
    float4 o;
    o.x = fmaf(v.x, w, bb.x);
    o.y = fmaf(v.y, w, bb.y);
    o.z = fmaf(v.z, w, bb.z);
    o.w = fmaf(v.w, w, bb.w);
    ((float4*)agg)[idx] = o;
}

// ---------------- edge scatter: agg[dst] += h[src] * dinv[src]*dinv[dst] ----------------
// One warp per edge; each lane handles cols {lane, lane+32, lane+64}.
__global__ void __launch_bounds__(256)
scatter_edges(const int* __restrict__ ei, const float* __restrict__ h,
              float* __restrict__ agg) {
    int e    = (blockIdx.x * blockDim.x + threadIdx.x) >> 5;
    int lane = threadIdx.x & 31;
    if (e >= NE) return;
    int s = __ldg(ei + e);        // src
    int d = __ldg(ei + NE + e);   // dst
    if ((unsigned)s >= NN || (unsigned)d >= NN) return;
    float norm = g_dinv[s] * g_dinv[d];
    const float* src = h + (size_t)s * DD;
    float* dstp = agg + (size_t)d * DD;
    float v0 = src[lane]      * norm;
    float v1 = src[lane + 32] * norm;
    float v2 = src[lane + 64] * norm;
    atomicAdd(dstp + lane,      v0);
    atomicAdd(dstp + lane + 32, v1);
    atomicAdd(dstp + lane + 64, v2);
}

// ---------------- pointwise: x = BN(LeakyReLU(agg)) ----------------
__global__ void leaky_bn(const float* __restrict__ agg, float* __restrict__ xout,
                         const float* __restrict__ gamma, const float* __restrict__ beta,
                         const float* __restrict__ mean,  const float* __restrict__ var) {
    int idx = blockIdx.x * blockDim.x + threadIdx.x;   // float4 index
    if (idx >= NN * D4) return;
    int c4 = idx % D4;
    float4 v = ((const float4*)agg)[idx];
    float4 G = ((const float4*)gamma)[c4];
    float4 B = ((const float4*)beta)[c4];
    float4 M = ((const float4*)mean)[c4];
    float4 V = ((const float4*)var)[c4];
    v.x = v.x >= 0.f ? v.x : 0.05f * v.x;
    v.y = v.y >= 0.f ? v.y : 0.05f * v.y;
    v.z = v.z >= 0.f ? v.z : 0.05f * v.z;
    v.w = v.w >= 0.f ? v.w : 0.05f * v.w;
    float4 o;
    o.x = fmaf((v.x - M.x) * rsqrtf(V.x + 1e-5f), G.x, B.x);
    o.y = fmaf((v.y - M.y) * rsqrtf(V.y + 1e-5f), G.y, B.y);
    o.z = fmaf((v.z - M.z) * rsqrtf(V.z + 1e-5f), G.z, B.z);
    o.w = fmaf((v.w - M.w) * rsqrtf(V.w + 1e-5f), G.w, B.w);
    ((float4*)xout)[idx] = o;
}

// ---------------- launcher ----------------
extern "C" void kernel_launch(void* const* d_in, const int* in_sizes, int n_in,
                              void* d_out, int out_size) {
    const float* X     = (const float*)d_in[0];
    const int*   ei    = (const int*)d_in[1];      // edge_index as int32 (harness dtype set)
    const float* W1    = (const float*)d_in[2];
    const float* b1    = (const float*)d_in[3];
    const float* W2    = (const float*)d_in[4];
    const float* b2    = (const float*)d_in[5];
    const float* gamma = (const float*)d_in[6];
    const float* beta  = (const float*)d_in[7];
    const float* mean  = (const float*)d_in[8];
    const float* var   = (const float*)d_in[9];
    float* out = (float*)d_out;

    void* p;
    cudaGetSymbolAddress(&p, g_h);   float* h   = (float*)p;
    cudaGetSymbolAddress(&p, g_agg); float* agg = (float*)p;

    const int TPB = 256;
    int nodeBlocks = (NN + TPB - 1) / TPB;
    int edgeBlocks = (NE + TPB - 1) / TPB;
    int vecBlocks  = (NN * D4 + TPB - 1) / TPB;
    int gemmBlocks = (NN + 63) / 64;
    int scatBlocks = NE / 8;   // 1 warp per edge, 8 warps per block

    // normalization
    zero_deg_kernel<<<nodeBlocks, TPB>>>();
    count_deg_kernel<<<edgeBlocks, TPB>>>(ei + NE);
    dinv_kernel<<<nodeBlocks, TPB>>>();

    // layer 1
    gemm96<<<gemmBlocks, TPB>>>(X, W1, h);
    selfloop_init<<<vecBlocks, TPB>>>(h, b1, agg);
    scatter_edges<<<scatBlocks, TPB>>>(ei, h, agg);
    leaky_bn<<<vecBlocks, TPB>>>(agg, h, gamma, beta, mean, var);  // x1 -> h (reuse)

    // layer 2 (aggregate directly into d_out)
    gemm96<<<gemmBlocks, TPB>>>(h, W2, agg);                        // h2 -> agg (reuse)
    selfloop_init<<<vecBlocks, TPB>>>(agg, b2, out);
    scatter_edges<<<scatBlocks, TPB>>>(ei, agg, out);
}

// round 4
// speedup vs baseline: 1.0020x; 1.0020x over previous
#include <cuda_runtime.h>
#include <math.h>

#define NN 100000
#define NE 800000
#define DD 96
#define D4 (DD/4)   // 24 float4 per row

// ---- scratch (static device globals; no allocation at runtime) ----
__device__ __align__(16) float g_h[(size_t)NN * DD];     // layer GEMM output (scatter source)
__device__ __align__(16) float g_agg[(size_t)NN * DD];   // aggregation buffer / h2
__device__ int   g_deg[NN];
__device__ float g_dinv[NN];

// ---------------- degree / norm ----------------
__global__ void zero_deg_kernel() {
    int i = blockIdx.x * blockDim.x + threadIdx.x;
    if (i < NN) g_deg[i] = 0;
}

__global__ void count_deg_kernel(const int* __restrict__ dst) {
    int e = blockIdx.x * blockDim.x + threadIdx.x;
    if (e < NE) {
        int d = dst[e];
        if ((unsigned)d < NN) atomicAdd(&g_deg[d], 1);
    }
}

__global__ void dinv_kernel() {
    int i = blockIdx.x * blockDim.x + threadIdx.x;
    if (i < NN) g_dinv[i] = rsqrtf((float)(g_deg[i] + 1));  // +1 self-loop
}

// ---------------- GEMM + fused self-loop epilogue ----------------
// h   = X @ W                      (scatter source)
// agg = h * dinv[r]^2 + bias       (self-loop term + bias, pre-initialized agg)
__global__ void __launch_bounds__(256, 1)
gemm96_fused(const float* __restrict__ X, const float* __restrict__ W,
             const float* __restrict__ bias,
             float* __restrict__ h, float* __restrict__ agg) {
    __shared__ float Ws[DD * DD];  // 36 KB
    for (int i = threadIdx.x; i < DD * DD / 4; i += 256)
        ((float4*)Ws)[i] = ((const float4*)W)[i];
    __syncthreads();

    const int tc   = threadIdx.x & 31;
    const int wid  = threadIdx.x >> 5;
    const int row0 = blockIdx.x * 64 + wid * 8;

    const float bb0 = bias[tc];
    const float bb1 = bias[tc + 32];
    const float bb2 = bias[tc + 64];

    float acc[8][3];
#pragma unroll
    for (int i = 0; i < 8; i++) { acc[i][0] = 0.f; acc[i][1] = 0.f; acc[i][2] = 0.f; }

#pragma unroll 1
    for (int k4 = 0; k4 < D4; k4++) {
        float b[4][3];
#pragma unroll
        for (int kk = 0; kk < 4; kk++) {
            int k = k4 * 4 + kk;
            b[kk][0] = Ws[k * DD + tc];
            b[kk][1] = Ws[k * DD + tc + 32];
            b[kk][2] = Ws[k * DD + tc + 64];
        }
#pragma unroll
        for (int i = 0; i < 8; i++) {
            int r = row0 + i;
            if (r < NN) {
                float4 a = ((const float4*)(X + (size_t)r * DD))[k4];
                acc[i][0] = fmaf(a.x, b[0][0], acc[i][0]);
                acc[i][1] = fmaf(a.x, b[0][1], acc[i][1]);
                acc[i][2] = fmaf(a.x, b[0][2], acc[i][2]);
                acc[i][0] = fmaf(a.y, b[1][0], acc[i][0]);
                acc[i][1] = fmaf(a.y, b[1][1], acc[i][1]);
                acc[i][2] = fmaf(a.y, b[1][2], acc[i][2]);
                acc[i][0] = fmaf(a.z, b[2][0], acc[i][0]);
                acc[i][1] = fmaf(a.z, b[2][1], acc[i][1]);
                acc[i][2] = fmaf(a.z, b[2][2], acc[i][2]);
                acc[i][0] = fmaf(a.w, b[3][0], acc[i][0]);
                acc[i][1] = fmaf(a.w, b[3][1], acc[i][1]);
                acc[i][2] = fmaf(a.w, b[3][2], acc[i][2]);
            }
        }
    }
#pragma unroll
    for (int i = 0; i < 8; i++) {
        int r = row0 + i;
        if (r < NN) {
            float di = g_dinv[r];
            float w  = di * di;
            size_t base = (size_t)r * DD;
            h[base + tc]      = acc[i][0];
            h[base + tc + 32] = acc[i][1];
            h[base + tc + 64] = acc[i][2];
            agg[base + tc]      = fmaf(acc[i][0], w, bb0);
            agg[base + tc + 32] = fmaf(acc[i][1], w, bb1);
            agg[base + tc + 64] = fmaf(acc[i][2], w, bb2);
        }
    }
}

// ---------------- edge scatter: agg[dst] += h[src] * dinv[src]*dinv[dst] ----------------
// One warp per edge; lanes 0..23 each handle one float4 via vector RED.
__global__ void __launch_bounds__(256)
scatter_edges(const int* __restrict__ ei, const float* __restrict__ h,
              float* __restrict__ agg) {
    int e    = (blockIdx.x * blockDim.x + threadIdx.x) >> 5;
    int lane = threadIdx.x & 31;
    if (e >= NE) return;
    int s = __ldg(ei + e);        // src
    int d = __ldg(ei + NE + e);   // dst
    if ((unsigned)s >= NN || (unsigned)d >= NN) return;
    float norm = g_dinv[s] * g_dinv[d];
    if (lane < D4) {
        float4 v = ((const float4*)(h + (size_t)s * DD))[lane];
        float* p = agg + (size_t)d * DD + lane * 4;
        asm volatile("red.global.add.v4.f32 [%0], {%1,%2,%3,%4};"
                     :: "l"(p), "f"(v.x * norm), "f"(v.y * norm),
                        "f"(v.z * norm), "f"(v.w * norm)
                     : "memory");
    }
}

// ---------------- pointwise: x = BN(LeakyReLU(agg)) ----------------
__global__ void leaky_bn(const float* __restrict__ agg, float* __restrict__ xout,
                         const float* __restrict__ gamma, const float* __restrict__ beta,
                         const float* __restrict__ mean,  const float* __restrict__ var) {
    int idx = blockIdx.x * blockDim.x + threadIdx.x;   // float4 index
    if (idx >= NN * D4) return;
    int c4 = idx % D4;
    float4 v = ((const float4*)agg)[idx];
    float4 G = ((const float4*)gamma)[c4];
    float4 B = ((const float4*)beta)[c4];
    float4 M = ((const float4*)mean)[c4];
    float4 V = ((const float4*)var)[c4];
    v.x = v.x >= 0.f ? v.x : 0.05f * v.x;
    v.y = v.y >= 0.f ? v.y : 0.05f * v.y;
    v.z = v.z >= 0.f ? v.z : 0.05f * v.z;
    v.w = v.w >= 0.f ? v.w : 0.05f * v.w;
    float4 o;
    o.x = fmaf((v.x - M.x) * rsqrtf(V.x + 1e-5f), G.x, B.x);
    o.y = fmaf((v.y - M.y) * rsqrtf(V.y + 1e-5f), G.y, B.y);
    o.z = fmaf((v.z - M.z) * rsqrtf(V.z + 1e-5f), G.z, B.z);
    o.w = fmaf((v.w - M.w) * rsqrtf(V.w + 1e-5f), G.w, B.w);
    ((float4*)xout)[idx] = o;
}

// ---------------- launcher ----------------
extern "C" void kernel_launch(void* const* d_in, const int* in_sizes, int n_in,
                              void* d_out, int out_size) {
    const float* X     = (const float*)d_in[0];
    const int*   ei    = (const int*)d_in[1];      // edge_index as int32
    const float* W1    = (const float*)d_in[2];
    const float* b1    = (const float*)d_in[3];
    const float* W2    = (const float*)d_in[4];
    const float* b2    = (const float*)d_in[5];
    const float* gamma = (const float*)d_in[6];
    const float* beta  = (const float*)d_in[7];
    const float* mean  = (const float*)d_in[8];
    const float* var   = (const float*)d_in[9];
    float* out = (float*)d_out;

    void* p;
    cudaGetSymbolAddress(&p, g_h);   float* h   = (float*)p;
    cudaGetSymbolAddress(&p, g_agg); float* agg = (float*)p;

    const int TPB = 256;
    int nodeBlocks = (NN + TPB - 1) / TPB;
    int edgeBlocks = (NE + TPB - 1) / TPB;
    int vecBlocks  = (NN * D4 + TPB - 1) / TPB;
    int gemmBlocks = (NN + 63) / 64;
    int scatBlocks = NE / 8;   // 1 warp per edge, 8 warps per block

    // normalization
    zero_deg_kernel<<<nodeBlocks, TPB>>>();
    count_deg_kernel<<<edgeBlocks, TPB>>>(ei + NE);
    dinv_kernel<<<nodeBlocks, TPB>>>();

    // layer 1: h = X@W1 ; agg = h*dinv^2 + b1 ; agg += edges ; h = BN(LReLU(agg))
    gemm96_fused<<<gemmBlocks, TPB>>>(X, W1, b1, h, agg);
    scatter_edges<<<scatBlocks, TPB>>>(ei, h, agg);
    leaky_bn<<<vecBlocks, TPB>>>(agg, h, gamma, beta, mean, var);  // x1 -> h (reuse)

    // layer 2: agg = h@W2 (h2) ; out = agg*dinv^2 + b2 ; out += edges
    gemm96_fused<<<gemmBlocks, TPB>>>(h, W2, b2, agg, out);
    scatter_edges<<<scatBlocks, TPB>>>(ei, agg, out);
}

// round 5
// speedup vs baseline: 1.4037x; 1.4010x over previous
#include <cuda_runtime.h>
#include <math.h>

#define NN 100000
#define NE 800000
#define DD 96
#define D4 (DD/4)   // 24 float4 per row
#define SCAN_B 1024
#define NB_SCAN ((NN + SCAN_B - 1) / SCAN_B)   // 98

// ---- scratch (static device globals; no allocation at runtime) ----
__device__ __align__(16) float g_h[(size_t)NN * DD];   // GEMM output (gather source)
__device__ __align__(16) float g_x1[(size_t)NN * DD];  // layer-1 activations
__device__ int   g_deg[NN];
__device__ float g_dinv[NN];
__device__ int   g_rowptr[NN + 1];
__device__ int   g_cursor[NN];
__device__ int   g_csr_src[NE];
__device__ int   g_blocksums[NB_SCAN];

// ---------------- degree / norm / CSR build ----------------
__global__ void zero_deg_kernel() {
    int i = blockIdx.x * blockDim.x + threadIdx.x;
    if (i < NN) g_deg[i] = 0;
}

__global__ void count_deg_kernel(const int* __restrict__ dst) {
    int e = blockIdx.x * blockDim.x + threadIdx.x;
    if (e < NE) {
        int d = dst[e];
        if ((unsigned)d < NN) atomicAdd(&g_deg[d], 1);
    }
}

__global__ void dinv_kernel() {
    int i = blockIdx.x * blockDim.x + threadIdx.x;
    if (i < NN) g_dinv[i] = rsqrtf((float)(g_deg[i] + 1));  // +1 self-loop
}

// block-wise exclusive scan of g_deg -> g_rowptr (partial), block sums out
__global__ void scan_block_kernel() {
    __shared__ int sh[SCAN_B];
    int i = blockIdx.x * SCAN_B + threadIdx.x;
    int v = (i < NN) ? g_deg[i] : 0;
    sh[threadIdx.x] = v;
    __syncthreads();
#pragma unroll
    for (int ofs = 1; ofs < SCAN_B; ofs <<= 1) {
        int t = (threadIdx.x >= ofs) ? sh[threadIdx.x - ofs] : 0;
        __syncthreads();
        sh[threadIdx.x] += t;
        __syncthreads();
    }
    if (i < NN) g_rowptr[i] = sh[threadIdx.x] - v;   // exclusive
    if (threadIdx.x == SCAN_B - 1) g_blocksums[blockIdx.x] = sh[SCAN_B - 1];
}

__global__ void scan_sums_kernel() {
    if (blockIdx.x == 0 && threadIdx.x == 0) {
        int run = 0;
        for (int i = 0; i < NB_SCAN; i++) { int v = g_blocksums[i]; g_blocksums[i] = run; run += v; }
    }
}

__global__ void scan_add_kernel() {
    int i = blockIdx.x * SCAN_B + threadIdx.x;
    if (i < NN) {
        int r = g_rowptr[i] + g_blocksums[blockIdx.x];
        g_rowptr[i] = r;
        g_cursor[i] = r;
    }
    if (i == 0) g_rowptr[NN] = NE;
}

__global__ void bin_edges_kernel(const int* __restrict__ ei) {
    int e = blockIdx.x * blockDim.x + threadIdx.x;
    if (e >= NE) return;
    int s = ei[e];
    int d = ei[NE + e];
    if ((unsigned)s >= NN || (unsigned)d >= NN) return;
    int pos = atomicAdd(&g_cursor[d], 1);
    g_csr_src[pos] = s;
}

// ---------------- GEMM: h[N,96] = X[N,96] @ W[96,96] ----------------
__global__ void __launch_bounds__(256, 1)
gemm96(const float* __restrict__ X, const float* __restrict__ W, float* __restrict__ out) {
    __shared__ float Ws[DD * DD];  // 36 KB
    for (int i = threadIdx.x; i < DD * DD / 4; i += 256)
        ((float4*)Ws)[i] = ((const float4*)W)[i];
    __syncthreads();

    const int tc   = threadIdx.x & 31;
    const int wid  = threadIdx.x >> 5;
    const int row0 = blockIdx.x * 64 + wid * 8;

    float acc[8][3];
#pragma unroll
    for (int i = 0; i < 8; i++) { acc[i][0] = 0.f; acc[i][1] = 0.f; acc[i][2] = 0.f; }

#pragma unroll 1
    for (int k4 = 0; k4 < D4; k4++) {
        float b[4][3];
#pragma unroll
        for (int kk = 0; kk < 4; kk++) {
            int k = k4 * 4 + kk;
            b[kk][0] = Ws[k * DD + tc];
            b[kk][1] = Ws[k * DD + tc + 32];
            b[kk][2] = Ws[k * DD + tc + 64];
        }
#pragma unroll
        for (int i = 0; i < 8; i++) {
            int r = row0 + i;
            if (r < NN) {
                float4 a = ((const float4*)(X + (size_t)r * DD))[k4];
                acc[i][0] = fmaf(a.x, b[0][0], acc[i][0]);
                acc[i][1] = fmaf(a.x, b[0][1], acc[i][1]);
                acc[i][2] = fmaf(a.x, b[0][2], acc[i][2]);
                acc[i][0] = fmaf(a.y, b[1][0], acc[i][0]);
                acc[i][1] = fmaf(a.y, b[1][1], acc[i][1]);
                acc[i][2] = fmaf(a.y, b[1][2], acc[i][2]);
                acc[i][0] = fmaf(a.z, b[2][0], acc[i][0]);
                acc[i][1] = fmaf(a.z, b[2][1], acc[i][1]);
                acc[i][2] = fmaf(a.z, b[2][2], acc[i][2]);
                acc[i][0] = fmaf(a.w, b[3][0], acc[i][0]);
                acc[i][1] = fmaf(a.w, b[3][1], acc[i][1]);
                acc[i][2] = fmaf(a.w, b[3][2], acc[i][2]);
            }
        }
    }
#pragma unroll
    for (int i = 0; i < 8; i++) {
        int r = row0 + i;
        if (r < NN) {
            out[(size_t)r * DD + tc]      = acc[i][0];
            out[(size_t)r * DD + tc + 32] = acc[i][1];
            out[(size_t)r * DD + tc + 64] = acc[i][2];
        }
    }
}

// ---------------- pull aggregation (one warp per node, 24 active lanes) ----------------
// acc = h[n]*dinv[n]^2 + bias + sum_{s in in(n)} h[s]*dinv[s]*dinv[n]
// BN=1: apply LeakyReLU + BatchNorm before store (layer 1).
template <int BN>
__global__ void __launch_bounds__(256)
gather_nodes(const float* __restrict__ h, const float* __restrict__ bias,
             const float* __restrict__ gamma, const float* __restrict__ beta,
             const float* __restrict__ mean,  const float* __restrict__ var,
             float* __restrict__ xout) {
    int n    = (blockIdx.x * blockDim.x + threadIdx.x) >> 5;
    int lane = threadIdx.x & 31;
    if (n >= NN || lane >= D4) return;

    float dn = g_dinv[n];
    float4 acc = ((const float4*)(h + (size_t)n * DD))[lane];
    float4 bb  = ((const float4*)bias)[lane];
    float w = dn * dn;
    acc.x = fmaf(acc.x, w, bb.x);
    acc.y = fmaf(acc.y, w, bb.y);
    acc.z = fmaf(acc.z, w, bb.z);
    acc.w = fmaf(acc.w, w, bb.w);

    int off = g_rowptr[n];
    int end = g_rowptr[n + 1];

    // 2-edge unrolled main loop for MLP
    for (; off + 1 < end; off += 2) {
        int s0 = g_csr_src[off];
        int s1 = g_csr_src[off + 1];
        float n0 = g_dinv[s0] * dn;
        float n1 = g_dinv[s1] * dn;
        float4 v0 = ((const float4*)(h + (size_t)s0 * DD))[lane];
        float4 v1 = ((const float4*)(h + (size_t)s1 * DD))[lane];
        acc.x = fmaf(v0.x, n0, acc.x);
        acc.y = fmaf(v0.y, n0, acc.y);
        acc.z = fmaf(v0.z, n0, acc.z);
        acc.w = fmaf(v0.w, n0, acc.w);
        acc.x = fmaf(v1.x, n1, acc.x);
        acc.y = fmaf(v1.y, n1, acc.y);
        acc.z = fmaf(v1.z, n1, acc.z);
        acc.w = fmaf(v1.w, n1, acc.w);
    }
    if (off < end) {
        int s0 = g_csr_src[off];
        float n0 = g_dinv[s0] * dn;
        float4 v0 = ((const float4*)(h + (size_t)s0 * DD))[lane];
        acc.x = fmaf(v0.x, n0, acc.x);
        acc.y = fmaf(v0.y, n0, acc.y);
        acc.z = fmaf(v0.z, n0, acc.z);
        acc.w = fmaf(v0.w, n0, acc.w);
    }

    if (BN) {
        float4 G = ((const float4*)gamma)[lane];
        float4 B = ((const float4*)beta)[lane];
        float4 M = ((const float4*)mean)[lane];
        float4 V = ((const float4*)var)[lane];
        acc.x = acc.x >= 0.f ? acc.x : 0.05f * acc.x;
        acc.y = acc.y >= 0.f ? acc.y : 0.05f * acc.y;
        acc.z = acc.z >= 0.f ? acc.z : 0.05f * acc.z;
        acc.w = acc.w >= 0.f ? acc.w : 0.05f * acc.w;
        acc.x = fmaf((acc.x - M.x) * rsqrtf(V.x + 1e-5f), G.x, B.x);
        acc.y = fmaf((acc.y - M.y) * rsqrtf(V.y + 1e-5f), G.y, B.y);
        acc.z = fmaf((acc.z - M.z) * rsqrtf(V.z + 1e-5f), G.z, B.z);
        acc.w = fmaf((acc.w - M.w) * rsqrtf(V.w + 1e-5f), G.w, B.w);
    }
    ((float4*)(xout + (size_t)n * DD))[lane] = acc;
}

// ---------------- launcher ----------------
extern "C" void kernel_launch(void* const* d_in, const int* in_sizes, int n_in,
                              void* d_out, int out_size) {
    const float* X     = (const float*)d_in[0];
    const int*   ei    = (const int*)d_in[1];      // edge_index as int32
    const float* W1    = (const float*)d_in[2];
    const float* b1    = (const float*)d_in[3];
    const float* W2    = (const float*)d_in[4];
    const float* b2    = (const float*)d_in[5];
    const float* gamma = (const float*)d_in[6];
    const float* beta  = (const float*)d_in[7];
    const float* mean  = (const float*)d_in[8];
    const float* var   = (const float*)d_in[9];
    float* out = (float*)d_out;

    void* p;
    cudaGetSymbolAddress(&p, g_h);  float* h  = (float*)p;
    cudaGetSymbolAddress(&p, g_x1); float* x1 = (float*)p;

    const int TPB = 256;
    int nodeBlocks = (NN + TPB - 1) / TPB;
    int edgeBlocks = (NE + TPB - 1) / TPB;
    int gemmBlocks = (NN + 63) / 64;
    int gathBlocks = (NN + 7) / 8;     // 8 warps (nodes) per block

    // CSR build (per launch; deterministic work)
    zero_deg_kernel<<<nodeBlocks, TPB>>>();
    count_deg_kernel<<<edgeBlocks, TPB>>>(ei + NE);
    dinv_kernel<<<nodeBlocks, TPB>>>();
    scan_block_kernel<<<NB_SCAN, SCAN_B>>>();
    scan_sums_kernel<<<1, 32>>>();
    scan_add_kernel<<<NB_SCAN, SCAN_B>>>();
    bin_edges_kernel<<<edgeBlocks, TPB>>>(ei);

    // layer 1: h = X@W1 ; x1 = BN(LReLU(gather(h) + selfloop + b1))
    gemm96<<<gemmBlocks, TPB>>>(X, W1, h);
    gather_nodes<1><<<gathBlocks, TPB>>>(h, b1, gamma, beta, mean, var, x1);

    // layer 2: h = x1@W2 ; out = gather(h) + selfloop + b2
    gemm96<<<gemmBlocks, TPB>>>(x1, W2, h);
    gather_nodes<0><<<gathBlocks, TPB>>>(h, b2, gamma, beta, mean, var, out);
}

// round 8
// speedup vs baseline: 2.0878x; 1.4873x over previous
#include <cuda_runtime.h>
#include <cuda_bf16.h>
#include <cstdint>
#include <stdint.h>
#include <math.h>

#define NN 100000
#define NE 800000
#define DD 96
#define D4 (DD/4)
#define SCAN_B 1024
#define NB_SCAN ((NN + SCAN_B - 1) / SCAN_B)
#define TM 128
#define NT ((NN + TM - 1) / TM)

// smem layout (bytes); padded row stride 104 bf16 = 208 B (conflict-free ldmatrix)
#define PADB 208
#define AH_OFF 0
#define AL_OFF (AH_OFF + TM * PADB)          // 26624
#define WH_OFF (AL_OFF + TM * PADB)          // 53248
#define WL_OFF (WH_OFF + DD * PADB)          // 73216
#define SMEM_TOTAL (WL_OFF + DD * PADB)      // 93184

// ---- scratch (static device globals) ----
__device__ __align__(16) float g_h[(size_t)NN * DD];
__device__ __align__(16) __nv_bfloat16 g_xh[(size_t)NN * DD];
__device__ __align__(16) __nv_bfloat16 g_xl[(size_t)NN * DD];
__device__ __align__(16) __nv_bfloat16 g_w1h[DD * DD], g_w1l[DD * DD];
__device__ __align__(16) __nv_bfloat16 g_w2h[DD * DD], g_w2l[DD * DD];
__device__ int   g_deg[NN];
__device__ float g_dinv[NN];
__device__ int   g_rowptr[NN + 1];
__device__ int   g_cursor[NN];
__device__ int   g_csr_src[NE];
__device__ int   g_blocksums[NB_SCAN];

__device__ __forceinline__ uint32_t smem_u32(const void* p) {
    uint32_t a;
    asm("{ .reg .u64 t; cvta.to.shared.u64 t, %1; cvt.u32.u64 %0, t; }" : "=r"(a) : "l"(p));
    return a;
}
__device__ __forceinline__ void ldsm4(uint32_t* r, uint32_t addr) {
    asm volatile("ldmatrix.sync.aligned.m8n8.x4.shared.b16 {%0,%1,%2,%3}, [%4];"
        : "=r"(r[0]), "=r"(r[1]), "=r"(r[2]), "=r"(r[3]) : "r"(addr));
}
__device__ __forceinline__ void ldsm4t(uint32_t* r, uint32_t addr) {
    asm volatile("ldmatrix.sync.aligned.m8n8.x4.trans.shared.b16 {%0,%1,%2,%3}, [%4];"
        : "=r"(r[0]), "=r"(r[1]), "=r"(r[2]), "=r"(r[3]) : "r"(addr));
}
__device__ __forceinline__ void mma16816(float* c, const uint32_t* a, uint32_t b0, uint32_t b1) {
    asm volatile("mma.sync.aligned.m16n8k16.row.col.f32.bf16.bf16.f32 "
        "{%0,%1,%2,%3}, {%4,%5,%6,%7}, {%8,%9}, {%0,%1,%2,%3};"
        : "+f"(c[0]), "+f"(c[1]), "+f"(c[2]), "+f"(c[3])
        : "r"(a[0]), "r"(a[1]), "r"(a[2]), "r"(a[3]), "r"(b0), "r"(b1));
}

// ---------------- degree / norm / CSR build ----------------
__global__ void zero_deg_kernel() {
    int i = blockIdx.x * blockDim.x + threadIdx.x;
    if (i < NN) g_deg[i] = 0;
}
__global__ void count_deg_kernel(const int* __restrict__ dst) {
    int e = blockIdx.x * blockDim.x + threadIdx.x;
    if (e < NE) { int d = dst[e]; if ((unsigned)d < NN) atomicAdd(&g_deg[d], 1); }
}
__global__ void dinv_kernel() {
    int i = blockIdx.x * blockDim.x + threadIdx.x;
    if (i < NN) g_dinv[i] = rsqrtf((float)(g_deg[i] + 1));
}
__global__ void scan_block_kernel() {
    __shared__ int sh[SCAN_B];
    int i = blockIdx.x * SCAN_B + threadIdx.x;
    int v = (i < NN) ? g_deg[i] : 0;
    sh[threadIdx.x] = v;
    __syncthreads();
#pragma unroll
    for (int ofs = 1; ofs < SCAN_B; ofs <<= 1) {
        int t = (threadIdx.x >= ofs) ? sh[threadIdx.x - ofs] : 0;
        __syncthreads();
        sh[threadIdx.x] += t;
        __syncthreads();
    }
    if (i < NN) g_rowptr[i] = sh[threadIdx.x] - v;
    if (threadIdx.x == SCAN_B - 1) g_blocksums[blockIdx.x] = sh[SCAN_B - 1];
}
__global__ void scan_sums_kernel() {
    if (blockIdx.x == 0 && threadIdx.x == 0) {
        int run = 0;
        for (int i = 0; i < NB_SCAN; i++) { int v = g_blocksums[i]; g_blocksums[i] = run; run += v; }
    }
}
__global__ void scan_add_kernel() {
    int i = blockIdx.x * SCAN_B + threadIdx.x;
    if (i < NN) { int r = g_rowptr[i] + g_blocksums[blockIdx.x]; g_rowptr[i] = r; g_cursor[i] = r; }
    if (i == 0) g_rowptr[NN] = NE;
}
__global__ void bin_edges_kernel(const int* __restrict__ ei) {
    int e = blockIdx.x * blockDim.x + threadIdx.x;
    if (e >= NE) return;
    int s = ei[e], d = ei[NE + e];
    if ((unsigned)s >= NN || (unsigned)d >= NN) return;
    g_csr_src[atomicAdd(&g_cursor[d], 1)] = s;
}

// ---------------- conversions ----------------
__global__ void convert_w(const float* __restrict__ W, __nv_bfloat16* __restrict__ wh,
                          __nv_bfloat16* __restrict__ wl) {
    int idx = blockIdx.x * blockDim.x + threadIdx.x;   // K-major [k][n], no transpose
    if (idx >= DD * DD) return;
    float v = W[idx];
    __nv_bfloat16 h = __float2bfloat16(v);
    wh[idx] = h;
    wl[idx] = __float2bfloat16(v - __bfloat162float(h));
}
__global__ void convert_x(const float* __restrict__ X) {
    int idx = blockIdx.x * blockDim.x + threadIdx.x;
    if (idx >= NN * D4) return;
    float4 v = ((const float4*)X)[idx];
    __nv_bfloat162 h0 = __floats2bfloat162_rn(v.x, v.y);
    __nv_bfloat162 h1 = __floats2bfloat162_rn(v.z, v.w);
    __nv_bfloat162 l0 = __floats2bfloat162_rn(v.x - __bfloat162float(h0.x), v.y - __bfloat162float(h0.y));
    __nv_bfloat162 l1 = __floats2bfloat162_rn(v.z - __bfloat162float(h1.x), v.w - __bfloat162float(h1.y));
    ((uint2*)g_xh)[idx] = make_uint2(*(uint32_t*)&h0, *(uint32_t*)&h1);
    ((uint2*)g_xl)[idx] = make_uint2(*(uint32_t*)&l0, *(uint32_t*)&l1);
}

// ---------------- mma.sync bf16-split GEMM: out[N,96] = x @ W ----------------
__global__ void __launch_bounds__(256, 2)
mma_gemm(const __nv_bfloat16* __restrict__ Xh, const __nv_bfloat16* __restrict__ Xl,
         const __nv_bfloat16* __restrict__ Wh, const __nv_bfloat16* __restrict__ Wl,
         float* __restrict__ out) {
    extern __shared__ __align__(16) char smem[];
    const int tid = threadIdx.x, w = tid >> 5, lane = tid & 31;

    // stage X tile: 256 threads, half-row each (48 bf16 = 6 uint4)
    {
        int r = tid >> 1, half = tid & 1;
        int gr = blockIdx.x * TM + r;
        uint4* dH = (uint4*)(smem + AH_OFF + r * PADB + half * 96);
        uint4* dL = (uint4*)(smem + AL_OFF + r * PADB + half * 96);
        if (gr < NN) {
            const uint4* sH = (const uint4*)(Xh + (size_t)gr * DD) + half * 6;
            const uint4* sL = (const uint4*)(Xl + (size_t)gr * DD) + half * 6;
#pragma unroll
            for (int i = 0; i < 6; i++) { dH[i] = sH[i]; dL[i] = sL[i]; }
        } else {
            uint4 z = make_uint4(0, 0, 0, 0);
#pragma unroll
            for (int i = 0; i < 6; i++) { dH[i] = z; dL[i] = z; }
        }
    }
    // stage W tiles: rows 0..95 -> Wh, 128..223 -> Wl
    if (tid < DD) {
        uint4* d = (uint4*)(smem + WH_OFF + tid * PADB);
        const uint4* s = (const uint4*)(Wh + (size_t)tid * DD);
#pragma unroll
        for (int i = 0; i < 12; i++) d[i] = s[i];
    } else if (tid >= 128 && tid < 128 + DD) {
        int r = tid - 128;
        uint4* d = (uint4*)(smem + WL_OFF + r * PADB);
        const uint4* s = (const uint4*)(Wl + (size_t)r * DD);
#pragma unroll
        for (int i = 0; i < 12; i++) d[i] = s[i];
    }
    __syncthreads();

    const uint32_t sb = smem_u32(smem);
    float acc[12][4];
#pragma unroll
    for (int t = 0; t < 12; t++)
#pragma unroll
        for (int q = 0; q < 4; q++) acc[t][q] = 0.f;

    // ldmatrix base addresses
    const uint32_t aH = sb + AH_OFF + (w * 16 + (lane & 15)) * PADB + (lane >> 4) * 16;
    const uint32_t aL = sb + AL_OFF + (w * 16 + (lane & 15)) * PADB + (lane >> 4) * 16;
    const uint32_t bH = sb + WH_OFF + (lane & 15) * PADB + (lane >> 4) * 16;
    const uint32_t bL = sb + WL_OFF + (lane & 15) * PADB + (lane >> 4) * 16;

#pragma unroll
    for (int ks = 0; ks < 6; ks++) {
        uint32_t ah[4], al[4];
        ldsm4(ah, aH + ks * 32);
        ldsm4(al, aL + ks * 32);
#pragma unroll
        for (int nb = 0; nb < 6; nb++) {
            uint32_t bh[4], bl[4];
            ldsm4t(bh, bH + ks * 16 * PADB + nb * 32);
            ldsm4t(bl, bL + ks * 16 * PADB + nb * 32);
            mma16816(acc[2 * nb],     ah, bh[0], bh[1]);
            mma16816(acc[2 * nb],     ah, bl[0], bl[1]);
            mma16816(acc[2 * nb],     al, bh[0], bh[1]);
            mma16816(acc[2 * nb + 1], ah, bh[2], bh[3]);
            mma16816(acc[2 * nb + 1], ah, bl[2], bl[3]);
            mma16816(acc[2 * nb + 1], al, bh[2], bh[3]);
        }
    }

    // epilogue: fragment c -> global
    int r0 = blockIdx.x * TM + w * 16 + (lane >> 2);
    int c0 = (lane & 3) * 2;
#pragma unroll
    for (int nt = 0; nt < 12; nt++) {
        int col = nt * 8 + c0;
        if (r0 < NN)
            *(float2*)(out + (size_t)r0 * DD + col) = make_float2(acc[nt][0], acc[nt][1]);
        if (r0 + 8 < NN)
            *(float2*)(out + (size_t)(r0 + 8) * DD + col) = make_float2(acc[nt][2], acc[nt][3]);
    }
}

// ---------------- pull aggregation (one warp per node, 24 active lanes) ----------------
template <int BN>
__global__ void __launch_bounds__(256)
gather_nodes(const float* __restrict__ h, const float* __restrict__ bias,
             const float* __restrict__ gamma, const float* __restrict__ beta,
             const float* __restrict__ mean,  const float* __restrict__ var,
             float* __restrict__ outf) {
    int n    = (blockIdx.x * blockDim.x + threadIdx.x) >> 5;
    int lane = threadIdx.x & 31;
    if (n >= NN || lane >= D4) return;

    float dn = g_dinv[n];
    float4 acc = ((const float4*)(h + (size_t)n * DD))[lane];
    float4 bb  = ((const float4*)bias)[lane];
    float w = dn * dn;
    acc.x = fmaf(acc.x, w, bb.x);
    acc.y = fmaf(acc.y, w, bb.y);
    acc.z = fmaf(acc.z, w, bb.z);
    acc.w = fmaf(acc.w, w, bb.w);

    int off = g_rowptr[n], end = g_rowptr[n + 1];
    for (; off + 1 < end; off += 2) {
        int s0 = g_csr_src[off], s1 = g_csr_src[off + 1];
        float n0 = g_dinv[s0] * dn, n1 = g_dinv[s1] * dn;
        float4 v0 = ((const float4*)(h + (size_t)s0 * DD))[lane];
        float4 v1 = ((const float4*)(h + (size_t)s1 * DD))[lane];
        acc.x = fmaf(v0.x, n0, acc.x); acc.y = fmaf(v0.y, n0, acc.y);
        acc.z = fmaf(v0.z, n0, acc.z); acc.w = fmaf(v0.w, n0, acc.w);
        acc.x = fmaf(v1.x, n1, acc.x); acc.y = fmaf(v1.y, n1, acc.y);
        acc.z = fmaf(v1.z, n1, acc.z); acc.w = fmaf(v1.w, n1, acc.w);
    }
    if (off < end) {
        int s0 = g_csr_src[off];
        float n0 = g_dinv[s0] * dn;
        float4 v0 = ((const float4*)(h + (size_t)s0 * DD))[lane];
        acc.x = fmaf(v0.x, n0, acc.x); acc.y = fmaf(v0.y, n0, acc.y);
        acc.z = fmaf(v0.z, n0, acc.z); acc.w = fmaf(v0.w, n0, acc.w);
    }

    if (BN) {
        float4 G = ((const float4*)gamma)[lane];
        float4 B = ((const float4*)beta)[lane];
        float4 M = ((const float4*)mean)[lane];
        float4 V = ((const float4*)var)[lane];
        acc.x = acc.x >= 0.f ? acc.x : 0.05f * acc.x;
        acc.y = acc.y >= 0.f ? acc.y : 0.05f * acc.y;
        acc.z = acc.z >= 0.f ? acc.z : 0.05f * acc.z;
        acc.w = acc.w >= 0.f ? acc.w : 0.05f * acc.w;
        acc.x = fmaf((acc.x - M.x) * rsqrtf(V.x + 1e-5f), G.x, B.x);
        acc.y = fmaf((acc.y - M.y) * rsqrtf(V.y + 1e-5f), G.y, B.y);
        acc.z = fmaf((acc.z - M.z) * rsqrtf(V.z + 1e-5f), G.z, B.z);
        acc.w = fmaf((acc.w - M.w) * rsqrtf(V.w + 1e-5f), G.w, B.w);
        __nv_bfloat162 h0 = __floats2bfloat162_rn(acc.x, acc.y);
        __nv_bfloat162 h1 = __floats2bfloat162_rn(acc.z, acc.w);
        __nv_bfloat162 l0 = __floats2bfloat162_rn(acc.x - __bfloat162float(h0.x), acc.y - __bfloat162float(h0.y));
        __nv_bfloat162 l1 = __floats2bfloat162_rn(acc.z - __bfloat162float(h1.x), acc.w - __bfloat162float(h1.y));
        ((uint2*)g_xh)[n * D4 + lane] = make_uint2(*(uint32_t*)&h0, *(uint32_t*)&h1);
        ((uint2*)g_xl)[n * D4 + lane] = make_uint2(*(uint32_t*)&l0, *(uint32_t*)&l1);
    } else {
        ((float4*)(outf + (size_t)n * DD))[lane] = acc;
    }
}

// ---------------- launcher ----------------
extern "C" void kernel_launch(void* const* d_in, const int* in_sizes, int n_in,
                              void* d_out, int out_size) {
    const float* X     = (const float*)d_in[0];
    const int*   ei    = (const int*)d_in[1];
    const float* W1    = (const float*)d_in[2];
    const float* b1    = (const float*)d_in[3];
    const float* W2    = (const float*)d_in[4];
    const float* b2    = (const float*)d_in[5];
    const float* gamma = (const float*)d_in[6];
    const float* beta  = (const float*)d_in[7];
    const float* mean  = (const float*)d_in[8];
    const float* var   = (const float*)d_in[9];
    float* out = (float*)d_out;

    void* p;
    cudaGetSymbolAddress(&p, g_h);   float* h = (float*)p;
    cudaGetSymbolAddress(&p, g_xh);  __nv_bfloat16* xh = (__nv_bfloat16*)p;
    cudaGetSymbolAddress(&p, g_xl);  __nv_bfloat16* xl = (__nv_bfloat16*)p;
    cudaGetSymbolAddress(&p, g_w1h); __nv_bfloat16* w1h = (__nv_bfloat16*)p;
    cudaGetSymbolAddress(&p, g_w1l); __nv_bfloat16* w1l = (__nv_bfloat16*)p;
    cudaGetSymbolAddress(&p, g_w2h); __nv_bfloat16* w2h = (__nv_bfloat16*)p;
    cudaGetSymbolAddress(&p, g_w2l); __nv_bfloat16* w2l = (__nv_bfloat16*)p;

    cudaFuncSetAttribute(mma_gemm, cudaFuncAttributeMaxDynamicSharedMemorySize, SMEM_TOTAL);

    const int TPB = 256;
    int nodeBlocks = (NN + TPB - 1) / TPB;
    int edgeBlocks = (NE + TPB - 1) / TPB;
    int vecBlocks  = (NN * D4 + TPB - 1) / TPB;
    int gathBlocks = (NN + 7) / 8;
    int wBlocks    = (DD * DD + TPB - 1) / TPB;

    // CSR build + norm
    zero_deg_kernel<<<nodeBlocks, TPB>>>();
    count_deg_kernel<<<edgeBlocks, TPB>>>(ei + NE);
    dinv_kernel<<<nodeBlocks, TPB>>>();
    scan_block_kernel<<<NB_SCAN, SCAN_B>>>();
    scan_sums_kernel<<<1, 32>>>();
    scan_add_kernel<<<NB_SCAN, SCAN_B>>>();
    bin_edges_kernel<<<edgeBlocks, TPB>>>(ei);

    // conversions
    convert_w<<<wBlocks, TPB>>>(W1, w1h, w1l);
    convert_w<<<wBlocks, TPB>>>(W2, w2h, w2l);
    convert_x<<<vecBlocks, TPB>>>(X);

    // layer 1
    mma_gemm<<<NT, 256, SMEM_TOTAL>>>(xh, xl, w1h, w1l, h);
    gather_nodes<1><<<gathBlocks, TPB>>>(h, b1, gamma, beta, mean, var, nullptr);

    // layer 2
    mma_gemm<<<NT, 256, SMEM_TOTAL>>>(xh, xl, w2h, w2l, h);
    gather_nodes<0><<<gathBlocks, TPB>>>(h, b2, gamma, beta, mean, var, out);
}

// round 9
// speedup vs baseline: 2.3377x; 1.1197x over previous
#include <cuda_runtime.h>
#include <cuda_bf16.h>
#include <cstdint>
#include <stdint.h>
#include <math.h>

#define NN 100000
#define NE 800000
#define DD 96
#define D4 (DD/4)
#define SCAN_B 1024
#define NB_SCAN ((NN + SCAN_B - 1) / SCAN_B)
#define TM 128
#define NT ((NN + TM - 1) / TM)

// smem layout (bytes); padded row stride 104 bf16 = 208 B (conflict-free ldmatrix)
#define PADB 208
#define AH_OFF 0
#define AL_OFF (AH_OFF + TM * PADB)
#define WH_OFF (AL_OFF + TM * PADB)
#define WL_OFF (WH_OFF + DD * PADB)
#define SMEM_TOTAL (WL_OFF + DD * PADB)      // 93184

// ---- scratch (static device globals) ----
__device__ __align__(16) float g_h[(size_t)NN * DD];            // h' = (xW)*dinv[row]
__device__ __align__(16) __nv_bfloat16 g_xh[(size_t)NN * DD];
__device__ __align__(16) __nv_bfloat16 g_xl[(size_t)NN * DD];
__device__ __align__(16) __nv_bfloat16 g_w1h[DD * DD], g_w1l[DD * DD];
__device__ __align__(16) __nv_bfloat16 g_w2h[DD * DD], g_w2l[DD * DD];
__device__ int   g_deg[NN];
__device__ float g_dinv[NN];
__device__ int   g_rowptr[NN + 1];
__device__ int   g_cursor[NN];
__device__ int   g_csr_src[NE];
__device__ int   g_blocksums[NB_SCAN];

__device__ __forceinline__ uint32_t smem_u32(const void* p) {
    uint32_t a;
    asm("{ .reg .u64 t; cvta.to.shared.u64 t, %1; cvt.u32.u64 %0, t; }" : "=r"(a) : "l"(p));
    return a;
}
__device__ __forceinline__ void ldsm4(uint32_t* r, uint32_t addr) {
    asm volatile("ldmatrix.sync.aligned.m8n8.x4.shared.b16 {%0,%1,%2,%3}, [%4];"
        : "=r"(r[0]), "=r"(r[1]), "=r"(r[2]), "=r"(r[3]) : "r"(addr));
}
__device__ __forceinline__ void ldsm4t(uint32_t* r, uint32_t addr) {
    asm volatile("ldmatrix.sync.aligned.m8n8.x4.trans.shared.b16 {%0,%1,%2,%3}, [%4];"
        : "=r"(r[0]), "=r"(r[1]), "=r"(r[2]), "=r"(r[3]) : "r"(addr));
}
__device__ __forceinline__ void mma16816(float* c, const uint32_t* a, uint32_t b0, uint32_t b1) {
    asm volatile("mma.sync.aligned.m16n8k16.row.col.f32.bf16.bf16.f32 "
        "{%0,%1,%2,%3}, {%4,%5,%6,%7}, {%8,%9}, {%0,%1,%2,%3};"
        : "+f"(c[0]), "+f"(c[1]), "+f"(c[2]), "+f"(c[3])
        : "r"(a[0]), "r"(a[1]), "r"(a[2]), "r"(a[3]), "r"(b0), "r"(b1));
}

// ---------------- degree / norm / CSR build ----------------
__global__ void zero_deg_kernel() {
    int i = blockIdx.x * blockDim.x + threadIdx.x;
    if (i < NN) g_deg[i] = 0;
}
__global__ void count_deg_kernel(const int* __restrict__ dst) {
    int e = blockIdx.x * blockDim.x + threadIdx.x;
    if (e < NE) { int d = dst[e]; if ((unsigned)d < NN) atomicAdd(&g_deg[d], 1); }
}
__global__ void scan_block_kernel() {
    __shared__ int sh[SCAN_B];
    int i = blockIdx.x * SCAN_B + threadIdx.x;
    int v = (i < NN) ? g_deg[i] : 0;
    sh[threadIdx.x] = v;
    __syncthreads();
#pragma unroll
    for (int ofs = 1; ofs < SCAN_B; ofs <<= 1) {
        int t = (threadIdx.x >= ofs) ? sh[threadIdx.x - ofs] : 0;
        __syncthreads();
        sh[threadIdx.x] += t;
        __syncthreads();
    }
    if (i < NN) g_rowptr[i] = sh[threadIdx.x] - v;
    if (threadIdx.x == SCAN_B - 1) g_blocksums[blockIdx.x] = sh[SCAN_B - 1];
}
__global__ void scan_sums_kernel() {
    if (blockIdx.x == 0 && threadIdx.x == 0) {
        int run = 0;
        for (int i = 0; i < NB_SCAN; i++) { int v = g_blocksums[i]; g_blocksums[i] = run; run += v; }
    }
}
__global__ void scan_add_kernel() {   // + dinv computation (fused)
    int i = blockIdx.x * SCAN_B + threadIdx.x;
    if (i < NN) {
        int r = g_rowptr[i] + g_blocksums[blockIdx.x];
        g_rowptr[i] = r;
        g_cursor[i] = r;
        g_dinv[i] = rsqrtf((float)(g_deg[i] + 1));
    }
    if (i == 0) g_rowptr[NN] = NE;
}
__global__ void bin_edges_kernel(const int* __restrict__ ei) {
    int e = blockIdx.x * blockDim.x + threadIdx.x;
    if (e >= NE) return;
    int s = ei[e], d = ei[NE + e];
    if ((unsigned)s >= NN || (unsigned)d >= NN) return;
    g_csr_src[atomicAdd(&g_cursor[d], 1)] = s;
}

// ---------------- weight conversion (both layers, one launch) ----------------
__global__ void convert_w2x(const float* __restrict__ W1, const float* __restrict__ W2) {
    int idx = blockIdx.x * blockDim.x + threadIdx.x;
    if (idx >= 2 * DD * DD) return;
    int which = idx >= DD * DD;
    int i = idx - which * DD * DD;
    float v = which ? W2[i] : W1[i];
    __nv_bfloat16 h = __float2bfloat16(v);
    __nv_bfloat16 l = __float2bfloat16(v - __bfloat162float(h));
    if (which) { g_w2h[i] = h; g_w2l[i] = l; }
    else       { g_w1h[i] = h; g_w1l[i] = l; }
}

// ---------------- mma.sync bf16-split GEMM: out[r,:] = (x @ W) * dinv[r] ----------------
// SPLIT=1: read fp32 X and split to bf16 hi/lo while staging.
// SPLIT=0: read pre-split g_xh/g_xl.
template <int SPLIT>
__global__ void __launch_bounds__(256, 2)
mma_gemm(const float* __restrict__ Xf,
         const __nv_bfloat16* __restrict__ Xh, const __nv_bfloat16* __restrict__ Xl,
         const __nv_bfloat16* __restrict__ Wh, const __nv_bfloat16* __restrict__ Wl,
         float* __restrict__ out) {
    extern __shared__ __align__(16) char smem[];
    const int tid = threadIdx.x, w = tid >> 5, lane = tid & 31;

    // stage X tile: 256 threads, half-row each (48 values)
    {
        int r = tid >> 1, half = tid & 1;
        int gr = blockIdx.x * TM + r;
        if (SPLIT) {
            uint2* dH = (uint2*)(smem + AH_OFF + r * PADB + half * 96);
            uint2* dL = (uint2*)(smem + AL_OFF + r * PADB + half * 96);
            if (gr < NN) {
                const float4* s = (const float4*)(Xf + (size_t)gr * DD) + half * 12;
#pragma unroll
                for (int i = 0; i < 12; i++) {
                    float4 v = s[i];
                    __nv_bfloat162 h0 = __floats2bfloat162_rn(v.x, v.y);
                    __nv_bfloat162 h1 = __floats2bfloat162_rn(v.z, v.w);
                    __nv_bfloat162 l0 = __floats2bfloat162_rn(v.x - __bfloat162float(h0.x),
                                                              v.y - __bfloat162float(h0.y));
                    __nv_bfloat162 l1 = __floats2bfloat162_rn(v.z - __bfloat162float(h1.x),
                                                              v.w - __bfloat162float(h1.y));
                    dH[i] = make_uint2(*(uint32_t*)&h0, *(uint32_t*)&h1);
                    dL[i] = make_uint2(*(uint32_t*)&l0, *(uint32_t*)&l1);
                }
            } else {
                uint2 z = make_uint2(0, 0);
#pragma unroll
                for (int i = 0; i < 12; i++) { dH[i] = z; dL[i] = z; }
            }
        } else {
            uint4* dH = (uint4*)(smem + AH_OFF + r * PADB + half * 96);
            uint4* dL = (uint4*)(smem + AL_OFF + r * PADB + half * 96);
            if (gr < NN) {
                const uint4* sH = (const uint4*)(Xh + (size_t)gr * DD) + half * 6;
                const uint4* sL = (const uint4*)(Xl + (size_t)gr * DD) + half * 6;
#pragma unroll
                for (int i = 0; i < 6; i++) { dH[i] = sH[i]; dL[i] = sL[i]; }
            } else {
                uint4 z = make_uint4(0, 0, 0, 0);
#pragma unroll
                for (int i = 0; i < 6; i++) { dH[i] = z; dL[i] = z; }
            }
        }
    }
    // stage W tiles
    if (tid < DD) {
        uint4* d = (uint4*)(smem + WH_OFF + tid * PADB);
        const uint4* s = (const uint4*)(Wh + (size_t)tid * DD);
#pragma unroll
        for (int i = 0; i < 12; i++) d[i] = s[i];
    } else if (tid >= 128 && tid < 128 + DD) {
        int r = tid - 128;
        uint4* d = (uint4*)(smem + WL_OFF + r * PADB);
        const uint4* s = (const uint4*)(Wl + (size_t)r * DD);
#pragma unroll
        for (int i = 0; i < 12; i++) d[i] = s[i];
    }
    __syncthreads();

    const uint32_t sb = smem_u32(smem);
    float acc[12][4];
#pragma unroll
    for (int t = 0; t < 12; t++)
#pragma unroll
        for (int q = 0; q < 4; q++) acc[t][q] = 0.f;

    const uint32_t aH = sb + AH_OFF + (w * 16 + (lane & 15)) * PADB + (lane >> 4) * 16;
    const uint32_t aL = sb + AL_OFF + (w * 16 + (lane & 15)) * PADB + (lane >> 4) * 16;
    const uint32_t bH = sb + WH_OFF + (lane & 15) * PADB + (lane >> 4) * 16;
    const uint32_t bL = sb + WL_OFF + (lane & 15) * PADB + (lane >> 4) * 16;

#pragma unroll
    for (int ks = 0; ks < 6; ks++) {
        uint32_t ah[4], al[4];
        ldsm4(ah, aH + ks * 32);
        ldsm4(al, aL + ks * 32);
#pragma unroll
        for (int nb = 0; nb < 6; nb++) {
            uint32_t bh[4], bl[4];
            ldsm4t(bh, bH + ks * 16 * PADB + nb * 32);
            ldsm4t(bl, bL + ks * 16 * PADB + nb * 32);
            mma16816(acc[2 * nb],     ah, bh[0], bh[1]);
            mma16816(acc[2 * nb],     ah, bl[0], bl[1]);
            mma16816(acc[2 * nb],     al, bh[0], bh[1]);
            mma16816(acc[2 * nb + 1], ah, bh[2], bh[3]);
            mma16816(acc[2 * nb + 1], ah, bl[2], bl[3]);
            mma16816(acc[2 * nb + 1], al, bh[2], bh[3]);
        }
    }

    // epilogue: scale by dinv[row] and store
    int r0 = blockIdx.x * TM + w * 16 + (lane >> 2);
    int c0 = (lane & 3) * 2;
    float d0 = (r0 < NN) ? g_dinv[r0] : 0.f;
    float d1 = (r0 + 8 < NN) ? g_dinv[r0 + 8] : 0.f;
#pragma unroll
    for (int nt = 0; nt < 12; nt++) {
        int col = nt * 8 + c0;
        if (r0 < NN)
            *(float2*)(out + (size_t)r0 * DD + col) = make_float2(acc[nt][0] * d0, acc[nt][1] * d0);
        if (r0 + 8 < NN)
            *(float2*)(out + (size_t)(r0 + 8) * DD + col) = make_float2(acc[nt][2] * d1, acc[nt][3] * d1);
    }
}

// ---------------- pull aggregation (one warp per node, 24 active lanes) ----------------
// h' rows are pre-scaled by dinv[src]. agg = dinv[n]*(h'[n] + sum h'[s]) + bias.
template <int BN>
__global__ void __launch_bounds__(256)
gather_nodes(const float* __restrict__ h, const float* __restrict__ bias,
             const float* __restrict__ gamma, const float* __restrict__ beta,
             const float* __restrict__ mean,  const float* __restrict__ var,
             float* __restrict__ outf) {
    int n    = (blockIdx.x * blockDim.x + threadIdx.x) >> 5;
    int lane = threadIdx.x & 31;
    if (n >= NN || lane >= D4) return;

    float4 acc = ((const float4*)(h + (size_t)n * DD))[lane];   // self term (pre-scaled)

    int off = g_rowptr[n], end = g_rowptr[n + 1];
    // 4-edge unrolled: pure float4 adds, 4 row-loads in flight
    for (; off + 3 < end; off += 4) {
        int s0 = g_csr_src[off],     s1 = g_csr_src[off + 1];
        int s2 = g_csr_src[off + 2], s3 = g_csr_src[off + 3];
        float4 v0 = ((const float4*)(h + (size_t)s0 * DD))[lane];
        float4 v1 = ((const float4*)(h + (size_t)s1 * DD))[lane];
        float4 v2 = ((const float4*)(h + (size_t)s2 * DD))[lane];
        float4 v3 = ((const float4*)(h + (size_t)s3 * DD))[lane];
        v0.x += v1.x; v0.y += v1.y; v0.z += v1.z; v0.w += v1.w;
        v2.x += v3.x; v2.y += v3.y; v2.z += v3.z; v2.w += v3.w;
        acc.x += v0.x + v2.x; acc.y += v0.y + v2.y;
        acc.z += v0.z + v2.z; acc.w += v0.w + v2.w;
    }
    for (; off < end; off++) {
        int s0 = g_csr_src[off];
        float4 v0 = ((const float4*)(h + (size_t)s0 * DD))[lane];
        acc.x += v0.x; acc.y += v0.y; acc.z += v0.z; acc.w += v0.w;
    }

    float dn = g_dinv[n];
    float4 bb = ((const float4*)bias)[lane];
    acc.x = fmaf(acc.x, dn, bb.x);
    acc.y = fmaf(acc.y, dn, bb.y);
    acc.z = fmaf(acc.z, dn, bb.z);
    acc.w = fmaf(acc.w, dn, bb.w);

    if (BN) {
        float4 G = ((const float4*)gamma)[lane];
        float4 B = ((const float4*)beta)[lane];
        float4 M = ((const float4*)mean)[lane];
        float4 V = ((const float4*)var)[lane];
        acc.x = acc.x >= 0.f ? acc.x : 0.05f * acc.x;
        acc.y = acc.y >= 0.f ? acc.y : 0.05f * acc.y;
        acc.z = acc.z >= 0.f ? acc.z : 0.05f * acc.z;
        acc.w = acc.w >= 0.f ? acc.w : 0.05f * acc.w;
        acc.x = fmaf((acc.x - M.x) * rsqrtf(V.x + 1e-5f), G.x, B.x);
        acc.y = fmaf((acc.y - M.y) * rsqrtf(V.y + 1e-5f), G.y, B.y);
        acc.z = fmaf((acc.z - M.z) * rsqrtf(V.z + 1e-5f), G.z, B.z);
        acc.w = fmaf((acc.w - M.w) * rsqrtf(V.w + 1e-5f), G.w, B.w);
        __nv_bfloat162 h0 = __floats2bfloat162_rn(acc.x, acc.y);
        __nv_bfloat162 h1 = __floats2bfloat162_rn(acc.z, acc.w);
        __nv_bfloat162 l0 = __floats2bfloat162_rn(acc.x - __bfloat162float(h0.x), acc.y - __bfloat162float(h0.y));
        __nv_bfloat162 l1 = __floats2bfloat162_rn(acc.z - __bfloat162float(h1.x), acc.w - __bfloat162float(h1.y));
        ((uint2*)g_xh)[n * D4 + lane] = make_uint2(*(uint32_t*)&h0, *(uint32_t*)&h1);
        ((uint2*)g_xl)[n * D4 + lane] = make_uint2(*(uint32_t*)&l0, *(uint32_t*)&l1);
    } else {
        ((float4*)(outf + (size_t)n * DD))[lane] = acc;
    }
}

// ---------------- launcher ----------------
extern "C" void kernel_launch(void* const* d_in, const int* in_sizes, int n_in,
                              void* d_out, int out_size) {
    const float* X     = (const float*)d_in[0];
    const int*   ei    = (const int*)d_in[1];
    const float* W1    = (const float*)d_in[2];
    const float* b1    = (const float*)d_in[3];
    const float* W2    = (const float*)d_in[4];
    const float* b2    = (const float*)d_in[5];
    const float* gamma = (const float*)d_in[6];
    const float* beta  = (const float*)d_in[7];
    const float* mean  = (const float*)d_in[8];
    const float* var   = (const float*)d_in[9];
    float* out = (float*)d_out;

    void* p;
    cudaGetSymbolAddress(&p, g_h);   float* h = (float*)p;
    cudaGetSymbolAddress(&p, g_xh);  __nv_bfloat16* xh = (__nv_bfloat16*)p;
    cudaGetSymbolAddress(&p, g_xl);  __nv_bfloat16* xl = (__nv_bfloat16*)p;
    cudaGetSymbolAddress(&p, g_w1h); __nv_bfloat16* w1h = (__nv_bfloat16*)p;
    cudaGetSymbolAddress(&p, g_w1l); __nv_bfloat16* w1l = (__nv_bfloat16*)p;
    cudaGetSymbolAddress(&p, g_w2h); __nv_bfloat16* w2h = (__nv_bfloat16*)p;
    cudaGetSymbolAddress(&p, g_w2l); __nv_bfloat16* w2l = (__nv_bfloat16*)p;

    cudaFuncSetAttribute(mma_gemm<0>, cudaFuncAttributeMaxDynamicSharedMemorySize, SMEM_TOTAL);
    cudaFuncSetAttribute(mma_gemm<1>, cudaFuncAttributeMaxDynamicSharedMemorySize, SMEM_TOTAL);

    const int TPB = 256;
    int nodeBlocks = (NN + TPB - 1) / TPB;
    int edgeBlocks = (NE + TPB - 1) / TPB;
    int gathBlocks = (NN + 7) / 8;
    int wBlocks    = (2 * DD * DD + TPB - 1) / TPB;

    // CSR build + norm (+ weight conversion)
    zero_deg_kernel<<<nodeBlocks, TPB>>>();
    count_deg_kernel<<<edgeBlocks, TPB>>>(ei + NE);
    scan_block_kernel<<<NB_SCAN, SCAN_B>>>();
    scan_sums_kernel<<<1, 32>>>();
    scan_add_kernel<<<NB_SCAN, SCAN_B>>>();   // includes dinv
    bin_edges_kernel<<<edgeBlocks, TPB>>>(ei);
    convert_w2x<<<wBlocks, TPB>>>(W1, W2);

    // layer 1: h' = (X@W1)*dinv ; x1 = BN(LReLU(dinv*(self+sum)+b1)) -> bf16 split
    mma_gemm<1><<<NT, 256, SMEM_TOTAL>>>(X, nullptr, nullptr, w1h, w1l, h);
    gather_nodes<1><<<gathBlocks, TPB>>>(h, b1, gamma, beta, mean, var, nullptr);

    // layer 2: h' = (x1@W2)*dinv ; out = dinv*(self+sum)+b2
    mma_gemm<0><<<NT, 256, SMEM_TOTAL>>>(nullptr, xh, xl, w2h, w2l, h);
    gather_nodes<0><<<gathBlocks, TPB>>>(h, b2, gamma, beta, mean, var, out);
}

// round 10
// speedup vs baseline: 2.5511x; 1.0913x over previous
#include <cuda_runtime.h>
#include <cuda_bf16.h>
#include <cstdint>
#include <stdint.h>
#include <math.h>

#define NN 100000
#define NE 800000
#define DD 96
#define D4 (DD/4)
#define SCAN_B 1024
#define NB_SCAN ((NN + SCAN_B - 1) / SCAN_B)
#define TM 128
#define NT ((NN + TM - 1) / TM)

#define PADB 208
#define AH_OFF 0
#define AL_OFF (AH_OFF + TM * PADB)
#define WH_OFF (AL_OFF + TM * PADB)
#define WL_OFF (WH_OFF + DD * PADB)
#define SMEM_TOTAL (WL_OFF + DD * PADB)      // 93184

// ---- scratch (static device globals) ----
__device__ __align__(16) float g_h[(size_t)NN * DD];            // h' = (xW)*dinv[row]
__device__ __align__(16) __nv_bfloat16 g_xh[(size_t)NN * DD];
__device__ __align__(16) __nv_bfloat16 g_xl[(size_t)NN * DD];
__device__ __align__(16) __nv_bfloat16 g_w1h[DD * DD], g_w1l[DD * DD];
__device__ __align__(16) __nv_bfloat16 g_w2h[DD * DD], g_w2l[DD * DD];
__device__ int   g_deg[NN];
__device__ float g_dinv[NN];
__device__ int   g_rowptr[NN + 1];
__device__ int   g_cursor[NN];
__device__ int   g_csr_src[NE];
__device__ int   g_blocksums[NB_SCAN];

__device__ __forceinline__ uint32_t smem_u32(const void* p) {
    uint32_t a;
    asm("{ .reg .u64 t; cvta.to.shared.u64 t, %1; cvt.u32.u64 %0, t; }" : "=r"(a) : "l"(p));
    return a;
}
__device__ __forceinline__ void ldsm4(uint32_t* r, uint32_t addr) {
    asm volatile("ldmatrix.sync.aligned.m8n8.x4.shared.b16 {%0,%1,%2,%3}, [%4];"
        : "=r"(r[0]), "=r"(r[1]), "=r"(r[2]), "=r"(r[3]) : "r"(addr));
}
__device__ __forceinline__ void ldsm4t(uint32_t* r, uint32_t addr) {
    asm volatile("ldmatrix.sync.aligned.m8n8.x4.trans.shared.b16 {%0,%1,%2,%3}, [%4];"
        : "=r"(r[0]), "=r"(r[1]), "=r"(r[2]), "=r"(r[3]) : "r"(addr));
}
__device__ __forceinline__ void mma16816(float* c, const uint32_t* a, uint32_t b0, uint32_t b1) {
    asm volatile("mma.sync.aligned.m16n8k16.row.col.f32.bf16.bf16.f32 "
        "{%0,%1,%2,%3}, {%4,%5,%6,%7}, {%8,%9}, {%0,%1,%2,%3};"
        : "+f"(c[0]), "+f"(c[1]), "+f"(c[2]), "+f"(c[3])
        : "r"(a[0]), "r"(a[1]), "r"(a[2]), "r"(a[3]), "r"(b0), "r"(b1));
}

// ---------------- degree / norm / CSR build ----------------
__global__ void count_deg_kernel(const int* __restrict__ dst) {
    int e = blockIdx.x * blockDim.x + threadIdx.x;
    if (e < NE) { int d = dst[e]; if ((unsigned)d < NN) atomicAdd(&g_deg[d], 1); }
}
__global__ void dinv_kernel() {
    int i = blockIdx.x * blockDim.x + threadIdx.x;
    if (i < NN) g_dinv[i] = rsqrtf((float)(g_deg[i] + 1));
}
__global__ void scan_block_kernel() {
    __shared__ int sh[SCAN_B];
    int i = blockIdx.x * SCAN_B + threadIdx.x;
    int v = (i < NN) ? g_deg[i] : 0;
    sh[threadIdx.x] = v;
    __syncthreads();
#pragma unroll
    for (int ofs = 1; ofs < SCAN_B; ofs <<= 1) {
        int t = (threadIdx.x >= ofs) ? sh[threadIdx.x - ofs] : 0;
        __syncthreads();
        sh[threadIdx.x] += t;
        __syncthreads();
    }
    if (i < NN) g_rowptr[i] = sh[threadIdx.x] - v;
    if (threadIdx.x == SCAN_B - 1) g_blocksums[blockIdx.x] = sh[SCAN_B - 1];
}
// parallel exclusive scan of the 98 block sums (128 threads, shfl)
__global__ void scan_sums_kernel() {
    __shared__ int wsum[4];
    int i = threadIdx.x;
    int v = (i < NB_SCAN) ? g_blocksums[i] : 0;
    int x = v;
#pragma unroll
    for (int o = 1; o < 32; o <<= 1) {
        int t = __shfl_up_sync(0xFFFFFFFFu, x, o);
        if ((i & 31) >= o) x += t;
    }
    if ((i & 31) == 31) wsum[i >> 5] = x;
    __syncthreads();
    if (i == 0) {
        int run = 0;
#pragma unroll
        for (int k = 0; k < 4; k++) { int t = wsum[k]; wsum[k] = run; run += t; }
    }
    __syncthreads();
    int excl = (x - v) + wsum[i >> 5];
    if (i < NB_SCAN) g_blocksums[i] = excl;
}
__global__ void scan_add_kernel() {
    int i = blockIdx.x * SCAN_B + threadIdx.x;
    if (i < NN) {
        int r = g_rowptr[i] + g_blocksums[blockIdx.x];
        g_rowptr[i] = r;
        g_cursor[i] = r;
    }
    if (i == 0) g_rowptr[NN] = NE;
}
__global__ void bin_edges_kernel(const int* __restrict__ ei) {
    int e = blockIdx.x * blockDim.x + threadIdx.x;
    if (e >= NE) return;
    int s = ei[e], d = ei[NE + e];
    if ((unsigned)s >= NN || (unsigned)d >= NN) return;
    g_csr_src[atomicAdd(&g_cursor[d], 1)] = s;
}

// ---------------- weight conversion (both layers, one launch) ----------------
__global__ void convert_w2x(const float* __restrict__ W1, const float* __restrict__ W2) {
    int idx = blockIdx.x * blockDim.x + threadIdx.x;
    if (idx >= 2 * DD * DD) return;
    int which = idx >= DD * DD;
    int i = idx - which * DD * DD;
    float v = which ? W2[i] : W1[i];
    __nv_bfloat16 h = __float2bfloat16(v);
    __nv_bfloat16 l = __float2bfloat16(v - __bfloat162float(h));
    if (which) { g_w2h[i] = h; g_w2l[i] = l; }
    else       { g_w1h[i] = h; g_w1l[i] = l; }
}

// ---------------- mma.sync bf16-split GEMM: out[r,:] = (x @ W) * dinv[r] ----------------
template <int SPLIT>
__global__ void __launch_bounds__(256, 2)
mma_gemm(const float* __restrict__ Xf,
         const __nv_bfloat16* __restrict__ Xh, const __nv_bfloat16* __restrict__ Xl,
         const __nv_bfloat16* __restrict__ Wh, const __nv_bfloat16* __restrict__ Wl,
         float* __restrict__ out) {
    extern __shared__ __align__(16) char smem[];
    const int tid = threadIdx.x, w = tid >> 5, lane = tid & 31;

    {
        int r = tid >> 1, half = tid & 1;
        int gr = blockIdx.x * TM + r;
        if (SPLIT) {
            uint2* dH = (uint2*)(smem + AH_OFF + r * PADB + half * 96);
            uint2* dL = (uint2*)(smem + AL_OFF + r * PADB + half * 96);
            if (gr < NN) {
                const float4* s = (const float4*)(Xf + (size_t)gr * DD) + half * 12;
#pragma unroll
                for (int i = 0; i < 12; i++) {
                    float4 v = s[i];
                    __nv_bfloat162 h0 = __floats2bfloat162_rn(v.x, v.y);
                    __nv_bfloat162 h1 = __floats2bfloat162_rn(v.z, v.w);
                    __nv_bfloat162 l0 = __floats2bfloat162_rn(v.x - __bfloat162float(h0.x),
                                                              v.y - __bfloat162float(h0.y));
                    __nv_bfloat162 l1 = __floats2bfloat162_rn(v.z - __bfloat162float(h1.x),
                                                              v.w - __bfloat162float(h1.y));
                    dH[i] = make_uint2(*(uint32_t*)&h0, *(uint32_t*)&h1);
                    dL[i] = make_uint2(*(uint32_t*)&l0, *(uint32_t*)&l1);
                }
            } else {
                uint2 z = make_uint2(0, 0);
#pragma unroll
                for (int i = 0; i < 12; i++) { dH[i] = z; dL[i] = z; }
            }
        } else {
            uint4* dH = (uint4*)(smem + AH_OFF + r * PADB + half * 96);
            uint4* dL = (uint4*)(smem + AL_OFF + r * PADB + half * 96);
            if (gr < NN) {
                const uint4* sH = (const uint4*)(Xh + (size_t)gr * DD) + half * 6;
                const uint4* sL = (const uint4*)(Xl + (size_t)gr * DD) + half * 6;
#pragma unroll
                for (int i = 0; i < 6; i++) { dH[i] = sH[i]; dL[i] = sL[i]; }
            } else {
                uint4 z = make_uint4(0, 0, 0, 0);
#pragma unroll
                for (int i = 0; i < 6; i++) { dH[i] = z; dL[i] = z; }
            }
        }
    }
    if (tid < DD) {
        uint4* d = (uint4*)(smem + WH_OFF + tid * PADB);
        const uint4* s = (const uint4*)(Wh + (size_t)tid * DD);
#pragma unroll
        for (int i = 0; i < 12; i++) d[i] = s[i];
    } else if (tid >= 128 && tid < 128 + DD) {
        int r = tid - 128;
        uint4* d = (uint4*)(smem + WL_OFF + r * PADB);
        const uint4* s = (const uint4*)(Wl + (size_t)r * DD);
#pragma unroll
        for (int i = 0; i < 12; i++) d[i] = s[i];
    }
    __syncthreads();

    const uint32_t sb = smem_u32(smem);
    float acc[12][4];
#pragma unroll
    for (int t = 0; t < 12; t++)
#pragma unroll
        for (int q = 0; q < 4; q++) acc[t][q] = 0.f;

    const uint32_t aH = sb + AH_OFF + (w * 16 + (lane & 15)) * PADB + (lane >> 4) * 16;
    const uint32_t aL = sb + AL_OFF + (w * 16 + (lane & 15)) * PADB + (lane >> 4) * 16;
    const uint32_t bH = sb + WH_OFF + (lane & 15) * PADB + (lane >> 4) * 16;
    const uint32_t bL = sb + WL_OFF + (lane & 15) * PADB + (lane >> 4) * 16;

#pragma unroll
    for (int ks = 0; ks < 6; ks++) {
        uint32_t ah[4], al[4];
        ldsm4(ah, aH + ks * 32);
        ldsm4(al, aL + ks * 32);
#pragma unroll
        for (int nb = 0; nb < 6; nb++) {
            uint32_t bh[4], bl[4];
            ldsm4t(bh, bH + ks * 16 * PADB + nb * 32);
            ldsm4t(bl, bL + ks * 16 * PADB + nb * 32);
            mma16816(acc[2 * nb],     ah, bh[0], bh[1]);
            mma16816(acc[2 * nb],     ah, bl[0], bl[1]);
            mma16816(acc[2 * nb],     al, bh[0], bh[1]);
            mma16816(acc[2 * nb + 1], ah, bh[2], bh[3]);
            mma16816(acc[2 * nb + 1], ah, bl[2], bl[3]);
            mma16816(acc[2 * nb + 1], al, bh[2], bh[3]);
        }
    }

    int r0 = blockIdx.x * TM + w * 16 + (lane >> 2);
    int c0 = (lane & 3) * 2;
    float d0 = (r0 < NN) ? g_dinv[r0] : 0.f;
    float d1 = (r0 + 8 < NN) ? g_dinv[r0 + 8] : 0.f;
#pragma unroll
    for (int nt = 0; nt < 12; nt++) {
        int col = nt * 8 + c0;
        if (r0 < NN)
            *(float2*)(out + (size_t)r0 * DD + col) = make_float2(acc[nt][0] * d0, acc[nt][1] * d0);
        if (r0 + 8 < NN)
            *(float2*)(out + (size_t)(r0 + 8) * DD + col) = make_float2(acc[nt][2] * d1, acc[nt][3] * d1);
    }
}

// ---------------- pull aggregation ----------------
template <int BN>
__global__ void __launch_bounds__(256)
gather_nodes(const float* __restrict__ h, const float* __restrict__ bias,
             const float* __restrict__ gamma, const float* __restrict__ beta,
             const float* __restrict__ mean,  const float* __restrict__ var,
             float* __restrict__ outf) {
    int n    = (blockIdx.x * blockDim.x + threadIdx.x) >> 5;
    int lane = threadIdx.x & 31;
    if (n >= NN || lane >= D4) return;

    float4 acc = ((const float4*)(h + (size_t)n * DD))[lane];

    int off = g_rowptr[n], end = g_rowptr[n + 1];
    for (; off + 3 < end; off += 4) {
        int s0 = g_csr_src[off],     s1 = g_csr_src[off + 1];
        int s2 = g_csr_src[off + 2], s3 = g_csr_src[off + 3];
        float4 v0 = ((const float4*)(h + (size_t)s0 * DD))[lane];
        float4 v1 = ((const float4*)(h + (size_t)s1 * DD))[lane];
        float4 v2 = ((const float4*)(h + (size_t)s2 * DD))[lane];
        float4 v3 = ((const float4*)(h + (size_t)s3 * DD))[lane];
        v0.x += v1.x; v0.y += v1.y; v0.z += v1.z; v0.w += v1.w;
        v2.x += v3.x; v2.y += v3.y; v2.z += v3.z; v2.w += v3.w;
        acc.x += v0.x + v2.x; acc.y += v0.y + v2.y;
        acc.z += v0.z + v2.z; acc.w += v0.w + v2.w;
    }
    for (; off < end; off++) {
        int s0 = g_csr_src[off];
        float4 v0 = ((const float4*)(h + (size_t)s0 * DD))[lane];
        acc.x += v0.x; acc.y += v0.y; acc.z += v0.z; acc.w += v0.w;
    }

    float dn = g_dinv[n];
    float4 bb = ((const float4*)bias)[lane];
    acc.x = fmaf(acc.x, dn, bb.x);
    acc.y = fmaf(acc.y, dn, bb.y);
    acc.z = fmaf(acc.z, dn, bb.z);
    acc.w = fmaf(acc.w, dn, bb.w);

    if (BN) {
        float4 G = ((const float4*)gamma)[lane];
        float4 B = ((const float4*)beta)[lane];
        float4 M = ((const float4*)mean)[lane];
        float4 V = ((const float4*)var)[lane];
        acc.x = acc.x >= 0.f ? acc.x : 0.05f * acc.x;
        acc.y = acc.y >= 0.f ? acc.y : 0.05f * acc.y;
        acc.z = acc.z >= 0.f ? acc.z : 0.05f * acc.z;
        acc.w = acc.w >= 0.f ? acc.w : 0.05f * acc.w;
        acc.x = fmaf((acc.x - M.x) * rsqrtf(V.x + 1e-5f), G.x, B.x);
        acc.y = fmaf((acc.y - M.y) * rsqrtf(V.y + 1e-5f), G.y, B.y);
        acc.z = fmaf((acc.z - M.z) * rsqrtf(V.z + 1e-5f), G.z, B.z);
        acc.w = fmaf((acc.w - M.w) * rsqrtf(V.w + 1e-5f), G.w, B.w);
        __nv_bfloat162 h0 = __floats2bfloat162_rn(acc.x, acc.y);
        __nv_bfloat162 h1 = __floats2bfloat162_rn(acc.z, acc.w);
        __nv_bfloat162 l0 = __floats2bfloat162_rn(acc.x - __bfloat162float(h0.x), acc.y - __bfloat162float(h0.y));
        __nv_bfloat162 l1 = __floats2bfloat162_rn(acc.z - __bfloat162float(h1.x), acc.w - __bfloat162float(h1.y));
        ((uint2*)g_xh)[n * D4 + lane] = make_uint2(*(uint32_t*)&h0, *(uint32_t*)&h1);
        ((uint2*)g_xl)[n * D4 + lane] = make_uint2(*(uint32_t*)&l0, *(uint32_t*)&l1);
    } else {
        ((float4*)(outf + (size_t)n * DD))[lane] = acc;
    }
}

// ---------------- launcher ----------------
extern "C" void kernel_launch(void* const* d_in, const int* in_sizes, int n_in,
                              void* d_out, int out_size) {
    const float* X     = (const float*)d_in[0];
    const int*   ei    = (const int*)d_in[1];
    const float* W1    = (const float*)d_in[2];
    const float* b1    = (const float*)d_in[3];
    const float* W2    = (const float*)d_in[4];
    const float* b2    = (const float*)d_in[5];
    const float* gamma = (const float*)d_in[6];
    const float* beta  = (const float*)d_in[7];
    const float* mean  = (const float*)d_in[8];
    const float* var   = (const float*)d_in[9];
    float* out = (float*)d_out;

    void* p;
    cudaGetSymbolAddress(&p, g_h);   float* h = (float*)p;
    cudaGetSymbolAddress(&p, g_xh);  __nv_bfloat16* xh = (__nv_bfloat16*)p;
    cudaGetSymbolAddress(&p, g_xl);  __nv_bfloat16* xl = (__nv_bfloat16*)p;
    cudaGetSymbolAddress(&p, g_w1h); __nv_bfloat16* w1h = (__nv_bfloat16*)p;
    cudaGetSymbolAddress(&p, g_w1l); __nv_bfloat16* w1l = (__nv_bfloat16*)p;
    cudaGetSymbolAddress(&p, g_w2h); __nv_bfloat16* w2h = (__nv_bfloat16*)p;
    cudaGetSymbolAddress(&p, g_w2l); __nv_bfloat16* w2l = (__nv_bfloat16*)p;
    void* degp; cudaGetSymbolAddress(&degp, g_deg);

    cudaFuncSetAttribute(mma_gemm<0>, cudaFuncAttributeMaxDynamicSharedMemorySize, SMEM_TOTAL);
    cudaFuncSetAttribute(mma_gemm<1>, cudaFuncAttributeMaxDynamicSharedMemorySize, SMEM_TOTAL);

    // side stream + events for fork-join overlap (created once, on the
    // uncaptured correctness call; reused thereafter)
    static cudaStream_t s2 = nullptr;
    static cudaEvent_t evA = nullptr, evD = nullptr, evG = nullptr;
    if (!s2) {
        cudaStreamCreate(&s2);
        cudaEventCreateWithFlags(&evA, cudaEventDisableTiming);
        cudaEventCreateWithFlags(&evD, cudaEventDisableTiming);
        cudaEventCreateWithFlags(&evG, cudaEventDisableTiming);
    }

    const int TPB = 256;
    int nodeBlocks = (NN + TPB - 1) / TPB;
    int edgeBlocks = (NE + TPB - 1) / TPB;
    int gathBlocks = (NN + 7) / 8;
    int wBlocks    = (2 * DD * DD + TPB - 1) / TPB;

    // ---- stream 0: degree -> dinv -> (fork) -> scan chain -> bin ----
    cudaEventRecord(evA, 0);                       // fork point for side stream
    cudaMemsetAsync(degp, 0, NN * sizeof(int), 0);
    count_deg_kernel<<<edgeBlocks, TPB>>>(ei + NE);
    dinv_kernel<<<nodeBlocks, TPB>>>();
    cudaEventRecord(evD, 0);                       // dinv ready

    scan_block_kernel<<<NB_SCAN, SCAN_B>>>();
    scan_sums_kernel<<<1, 128>>>();
    scan_add_kernel<<<NB_SCAN, SCAN_B>>>();
    bin_edges_kernel<<<edgeBlocks, TPB>>>(ei);

    // ---- stream s2: weight conversion + layer-1 GEMM (overlaps scan/bin) ----
    cudaStreamWaitEvent(s2, evA, 0);
    convert_w2x<<<wBlocks, TPB, 0, s2>>>(W1, W2);
    cudaStreamWaitEvent(s2, evD, 0);               // epilogue needs dinv
    mma_gemm<1><<<NT, 256, SMEM_TOTAL, s2>>>(X, nullptr, nullptr, w1h, w1l, h);
    cudaEventRecord(evG, s2);

    // ---- join: gather1 needs CSR (stream 0) + h' (s2) ----
    cudaStreamWaitEvent(0, evG, 0);
    gather_nodes<1><<<gathBlocks, TPB>>>(h, b1, gamma, beta, mean, var, nullptr);

    // layer 2 (serial)
    mma_gemm<0><<<NT, 256, SMEM_TOTAL>>>(nullptr, xh, xl, w2h, w2l, h);
    gather_nodes<0><<<gathBlocks, TPB>>>(h, b2, gamma, beta, mean, var, out);
}